// round 6
// baseline (speedup 1.0000x reference)
#include <cuda_runtime.h>
#include <cuda_bf16.h>
#include <math.h>
#include <stdint.h>

#define BATCH 2
#define SEQ   2048
#define DIM   4096
#define NH    32
#define NKV   8
#define HD    128
#define MROWS 4096   // BATCH*SEQ
#define KVDIM 1024   // NKV*HD
#define K3    (3 * DIM)   // 12288: split-interleaved K

// ---------------- scratch (zero-init .bss, no runtime allocation) ----------
__device__ float g_q[(size_t)MROWS * DIM];
__device__ float g_k[(size_t)MROWS * KVDIM];
__device__ float g_v[(size_t)MROWS * KVDIM];
__device__ float g_attn[(size_t)MROWS * DIM];

__device__ uint16_t g_xs [(size_t)MROWS * K3];   // x split (A-side)
__device__ uint16_t g_as [(size_t)MROWS * K3];   // attn-out split (A-side)
__device__ uint16_t g_wqs[(size_t)DIM   * K3];   // weight splits (B-side)
__device__ uint16_t g_wks[(size_t)KVDIM * K3];
__device__ uint16_t g_wvs[(size_t)KVDIM * K3];
__device__ uint16_t g_wos[(size_t)DIM   * K3];

// attention split operands
__device__ uint16_t g_qs2[(size_t)BATCH * NH  * SEQ * 384];
__device__ uint16_t g_ks2[(size_t)BATCH * NKV * SEQ * 384];
__device__ uint16_t g_vs2[(size_t)BATCH * NKV * (3*SEQ) * HD];

// ---------------- helpers ---------------------------------------------------
__device__ __forceinline__ uint32_t smem_u32(const void* p) {
    return (uint32_t)__cvta_generic_to_shared(p);
}
__device__ __forceinline__ void cp_async16(uint32_t dst, const void* src) {
    asm volatile("cp.async.cg.shared.global [%0], [%1], 16;" :: "r"(dst), "l"(src) : "memory");
}
__device__ __forceinline__ void cp_commit() {
    asm volatile("cp.async.commit_group;" ::: "memory");
}

#define LDSM_X4(r0, r1, r2, r3, addr) \
    asm volatile("ldmatrix.sync.aligned.m8n8.x4.shared.b16 {%0,%1,%2,%3}, [%4];" \
                 : "=r"(r0), "=r"(r1), "=r"(r2), "=r"(r3) : "r"(addr))

#define LDSM_X4_T(r0, r1, r2, r3, addr) \
    asm volatile("ldmatrix.sync.aligned.m8n8.x4.trans.shared.b16 {%0,%1,%2,%3}, [%4];" \
                 : "=r"(r0), "=r"(r1), "=r"(r2), "=r"(r3) : "r"(addr))

#define MMA_BF16(d, a, b0v, b1v) \
    asm volatile("mma.sync.aligned.m16n8k16.row.col.f32.bf16.bf16.f32 " \
                 "{%0,%1,%2,%3}, {%4,%5,%6,%7}, {%8,%9}, {%0,%1,%2,%3};" \
                 : "+f"((d)[0]), "+f"((d)[1]), "+f"((d)[2]), "+f"((d)[3]) \
                 : "r"((a)[0]), "r"((a)[1]), "r"((a)[2]), "r"((a)[3]), \
                   "r"(b0v), "r"(b1v))

// ---------------------------------------------------------------------------
// Split fp32 -> bf16 triplets. AMODE=1: (hi,lo,hi); AMODE=0: (hi,hi,lo).
// ---------------------------------------------------------------------------
template <int AMODE>
__global__ void split_kernel(const float* __restrict__ src, uint16_t* __restrict__ dst,
                             int total8)
{
    int t = blockIdx.x * blockDim.x + threadIdx.x;
    if (t >= total8) return;
    float4 v0 = *(const float4*)&src[(size_t)t * 8];
    float4 v1 = *(const float4*)&src[(size_t)t * 8 + 4];
    float f[8] = {v0.x, v0.y, v0.z, v0.w, v1.x, v1.y, v1.z, v1.w};
    __align__(16) uint16_t o[24];
#pragma unroll
    for (int j = 0; j < 8; j++) {
        __nv_bfloat16 hi = __float2bfloat16_rn(f[j]);
        __nv_bfloat16 lo = __float2bfloat16_rn(f[j] - __bfloat162float(hi));
        uint16_t hb = __bfloat16_as_ushort(hi);
        uint16_t lb = __bfloat16_as_ushort(lo);
        if (AMODE) { o[3*j] = hb; o[3*j+1] = lb; o[3*j+2] = hb; }
        else       { o[3*j] = hb; o[3*j+1] = hb; o[3*j+2] = lb; }
    }
    uint4* dp = (uint4*)&dst[(size_t)t * 24];
    dp[0] = *(uint4*)&o[0];
    dp[1] = *(uint4*)&o[8];
    dp[2] = *(uint4*)&o[16];
}

// ---------------------------------------------------------------------------
// HMMA bf16 GEMM: C[m,n] = sum_{k'} A[m,k'] * B[n,k'], K' = K3.
// CTA tile 256(M) x 128(N), 8 warps = 4(m) x 2(n), warp tile 64x64.
// 4-stage cp.async pipeline; K chunk = 32 bf16; 80B rows (conflict-free ldsm).
// ---------------------------------------------------------------------------
#define BKC         32
#define ROW_BYTES   80
#define TROWS       384                   // 256 A rows + 128 B rows
#define STAGE_BYTES (TROWS * ROW_BYTES)   // 30720
#define NSTAGE      4
#define GSMEM       (NSTAGE * STAGE_BYTES)  // 122880
#define NITER       (K3 / BKC)            // 384

__global__ void __launch_bounds__(256, 1) gemm_hmma(
    const uint16_t* __restrict__ A, const uint16_t* __restrict__ Bm,
    float* __restrict__ C, int M, int N)
{
    extern __shared__ __align__(1024) char smem[];
    const uint32_t sbase = smem_u32(smem);

    const int bm = blockIdx.y * 256;
    const int bn = blockIdx.x * 128;
    const int tid = threadIdx.x;
    const int wid = tid >> 5;
    const int lane = tid & 31;
    const int wm = wid & 3;     // M quadrant (64 rows)
    const int wn = wid >> 2;    // N half (64 cols)

    const uint16_t* ga0 = A  + (size_t)bm * K3;
    const uint16_t* gb0 = Bm + (size_t)bn * K3;

    const int lc = tid & 3;          // 16B chunk within 64B row
    const int lr = tid >> 2;         // 0..63

    auto load_stage = [&](int s, int chunk) {
        const uint32_t sa = sbase + (uint32_t)s * STAGE_BYTES;
        const size_t koff = (size_t)chunk * BKC + lc * 8;
#pragma unroll
        for (int j = 0; j < 6; j++) {
            int r = lr + j * 64;     // 0..383
            const uint16_t* src = (r < 256)
                ? ga0 + (size_t)r * K3 + koff
                : gb0 + (size_t)(r - 256) * K3 + koff;
            cp_async16(sa + (uint32_t)(r * ROW_BYTES + lc * 16), src);
        }
        cp_commit();
    };

    float d[4][8][4];
#pragma unroll
    for (int mi = 0; mi < 4; mi++)
#pragma unroll
        for (int nj = 0; nj < 8; nj++)
#pragma unroll
            for (int q = 0; q < 4; q++) d[mi][nj][q] = 0.0f;

    const int grp  = lane >> 3;
    const int lrow = lane & 7;
    const int a_r = lrow + ((grp & 1) << 3);
    const int a_c = (grp >> 1) << 3;
    const int b_r = lrow + ((grp >> 1) << 3);
    const int b_c = (grp & 1) << 3;

    load_stage(0, 0);
    load_stage(1, 1);
    load_stage(2, 2);

    for (int i = 0; i < NITER; i++) {
        const int s = i & (NSTAGE - 1);
        asm volatile("cp.async.wait_group %0;" :: "n"(NSTAGE - 2) : "memory");
        __syncthreads();
        if (i + 3 < NITER) load_stage((i + 3) & (NSTAGE - 1), i + 3);
        else cp_commit();

        const uint32_t aB = sbase + (uint32_t)s * STAGE_BYTES;
        const uint32_t bB = aB + 256 * ROW_BYTES;
#pragma unroll
        for (int step = 0; step < 2; step++) {
            uint32_t af[4][4];
#pragma unroll
            for (int mi = 0; mi < 4; mi++) {
                uint32_t addr = aB + (uint32_t)((wm * 64 + mi * 16 + a_r) * ROW_BYTES
                                                + (step * 16 + a_c) * 2);
                LDSM_X4(af[mi][0], af[mi][1], af[mi][2], af[mi][3], addr);
            }
#pragma unroll
            for (int njp = 0; njp < 4; njp++) {
                uint32_t b0, b1, b2, b3;
                uint32_t addr = bB + (uint32_t)((wn * 64 + njp * 16 + b_r) * ROW_BYTES
                                                + (step * 16 + b_c) * 2);
                LDSM_X4(b0, b1, b2, b3, addr);
#pragma unroll
                for (int mi = 0; mi < 4; mi++) {
                    MMA_BF16(d[mi][2 * njp],     af[mi], b0, b1);
                    MMA_BF16(d[mi][2 * njp + 1], af[mi], b2, b3);
                }
            }
        }
    }

    const int er = lane >> 2;
    const int ec = (lane & 3) * 2;
#pragma unroll
    for (int mi = 0; mi < 4; mi++) {
#pragma unroll
        for (int nj = 0; nj < 8; nj++) {
            int r0 = bm + wm * 64 + mi * 16 + er;
            int c0 = bn + wn * 64 + nj * 8 + ec;
            *(float2*)&C[(size_t)r0 * N + c0]       = make_float2(d[mi][nj][0], d[mi][nj][1]);
            *(float2*)&C[(size_t)(r0 + 8) * N + c0] = make_float2(d[mi][nj][2], d[mi][nj][3]);
        }
    }
}

// ---------------------------------------------------------------------------
// RoPE + split for Q (A-side triplets, folds 1/sqrt(HD) scale) and K (B-side).
// ---------------------------------------------------------------------------
template <int ISQ>
__global__ void rope_split(const float* __restrict__ src, uint16_t* __restrict__ dst,
                           const float* __restrict__ fc, const float* __restrict__ fs)
{
    const int HEADS = ISQ ? NH : NKV;
    int gid = blockIdx.x * blockDim.x + threadIdx.x;
    int part = gid & 15;
    int row  = gid >> 4;
    int s = row & (SEQ - 1);
    int bh = row >> 11;
    int h = bh % HEADS;
    int b = bh / HEADS;
    const float scale = ISQ ? 0.08838834764831845f : 1.0f;

    const float* in = src + ((size_t)(b * SEQ + s)) * (HEADS * HD) + h * HD + part * 8;
    float vals[8];
    *(float4*)&vals[0] = *(const float4*)&in[0];
    *(float4*)&vals[4] = *(const float4*)&in[4];

    __align__(16) uint16_t o[24];
#pragma unroll
    for (int p = 0; p < 4; p++) {
        int i = part * 4 + p;
        float c  = fc[s * 64 + i];
        float sn = fs[s * 64 + i];
        float xr = vals[2 * p], xi = vals[2 * p + 1];
        float rr = (xr * c - xi * sn) * scale;
        float ri = (xr * sn + xi * c) * scale;
        float f2[2] = {rr, ri};
#pragma unroll
        for (int e = 0; e < 2; e++) {
            __nv_bfloat16 hi = __float2bfloat16_rn(f2[e]);
            __nv_bfloat16 lo = __float2bfloat16_rn(f2[e] - __bfloat162float(hi));
            uint16_t hb = __bfloat16_as_ushort(hi);
            uint16_t lb = __bfloat16_as_ushort(lo);
            int j = p * 2 + e;
            if (ISQ) { o[3*j] = hb; o[3*j+1] = lb; o[3*j+2] = hb; }
            else     { o[3*j] = hb; o[3*j+1] = hb; o[3*j+2] = lb; }
        }
    }
    uint4* dp = (uint4*)(dst + (size_t)row * 384 + part * 24);
    dp[0] = *(uint4*)&o[0];
    dp[1] = *(uint4*)&o[8];
    dp[2] = *(uint4*)&o[16];
}

// ---------------------------------------------------------------------------
// V split: rows 3t,3t+1 = hi, 3t+2 = lo.
// ---------------------------------------------------------------------------
__global__ void split_v_kernel(const float* __restrict__ src, uint16_t* __restrict__ dst)
{
    int gid = blockIdx.x * blockDim.x + threadIdx.x;
    int part = gid & 15;
    int row  = gid >> 4;
    int t = row & (SEQ - 1);
    int bkv = row >> 11;
    int kv = bkv & (NKV - 1);
    int b = bkv >> 3;

    const float* in = src + ((size_t)(b * SEQ + t)) * KVDIM + kv * HD + part * 8;
    float vals[8];
    *(float4*)&vals[0] = *(const float4*)&in[0];
    *(float4*)&vals[4] = *(const float4*)&in[4];

    __align__(16) uint16_t hi8[8], lo8[8];
#pragma unroll
    for (int j = 0; j < 8; j++) {
        __nv_bfloat16 hi = __float2bfloat16_rn(vals[j]);
        __nv_bfloat16 lo = __float2bfloat16_rn(vals[j] - __bfloat162float(hi));
        hi8[j] = __bfloat16_as_ushort(hi);
        lo8[j] = __bfloat16_as_ushort(lo);
    }
    uint16_t* out = dst + ((size_t)bkv * (3 * SEQ) + 3 * t) * HD + part * 8;
    *(uint4*)&out[0]        = *(uint4*)&hi8[0];
    *(uint4*)&out[HD]       = *(uint4*)&hi8[0];
    *(uint4*)&out[2 * HD]   = *(uint4*)&lo8[0];
}

// ---------------------------------------------------------------------------
// HMMA causal flash attention (unchanged from R5; proven at ~700us)
// ---------------------------------------------------------------------------
#define SQ_STR   784
#define SK_STR   784
#define SV_STR   272
#define SP_STR   400
#define SQ_OFF   0
#define SK_OFF   50176
#define SV_OFF   100352
#define SP_OFF   152576
#define ATT_SMEM 178176

__global__ void __launch_bounds__(256) attn_mma(
    const uint16_t* __restrict__ Qs, const uint16_t* __restrict__ Ks,
    const uint16_t* __restrict__ Vs, float* __restrict__ Oout)
{
    extern __shared__ __align__(1024) char smem[];
    const uint32_t sQ = smem_u32(smem) + SQ_OFF;
    const uint32_t sK = smem_u32(smem) + SK_OFF;
    const uint32_t sV = smem_u32(smem) + SV_OFF;
    const uint32_t sP = smem_u32(smem) + SP_OFF;
    float* mergeO = (float*)smem;
    float* mergeM = (float*)(smem + 32768);
    float* mergeL = (float*)(smem + 32768 + 256);

    const int qi = (SEQ / 64 - 1) - blockIdx.x;
    const int bh = blockIdx.y;
    const int b = bh >> 5, h = bh & 31, kvh = h >> 2;
    const int q0 = qi * 64;
    const int tid = threadIdx.x;
    const int wid = tid >> 5, lane = tid & 31;
    const int wm = wid & 3, wn = wid >> 2;
    const int grp = lane >> 3, lrow = lane & 7;

    const uint16_t* gq = Qs + ((size_t)(b * NH + h) * SEQ + q0) * 384;
#pragma unroll
    for (int j = 0; j < 12; j++) {
        int id = tid + j * 256;
        int r = id / 48, c = id % 48;
        cp_async16(sQ + (uint32_t)(r * SQ_STR + c * 16), gq + (size_t)r * 384 + c * 8);
    }
    cp_commit();

    float m0 = -1e30f, m1 = -1e30f, l0 = 0.0f, l1 = 0.0f;
    float Oc[16][4];
#pragma unroll
    for (int j = 0; j < 16; j++)
#pragma unroll
        for (int q = 0; q < 4; q++) Oc[j][q] = 0.0f;

    const uint16_t* gk = Ks + ((size_t)(b * NKV + kvh) * SEQ) * 384;
    const uint16_t* gv = Vs + ((size_t)(b * NKV + kvh) * (3 * SEQ)) * HD;

    const int ra = wm * 16 + (lane >> 2);

    for (int kt = 0; kt <= qi; kt++) {
        const int t0 = kt * 64;
        __syncthreads();
#pragma unroll
        for (int j = 0; j < 12; j++) {
            int id = tid + j * 256;
            int r = id / 48, c = id % 48;
            cp_async16(sK + (uint32_t)(r * SK_STR + c * 16),
                       gk + ((size_t)(t0 + r)) * 384 + c * 8);
        }
#pragma unroll
        for (int j = 0; j < 12; j++) {
            int id = tid + j * 256;
            int r = id / 16, c = id % 16;
            cp_async16(sV + (uint32_t)(r * SV_STR + c * 16),
                       gv + ((size_t)(t0 * 3 + r)) * HD + c * 8);
        }
        cp_commit();
        asm volatile("cp.async.wait_group 0;" ::: "memory");
        __syncthreads();

        float Sa[4][4];
#pragma unroll
        for (int nt = 0; nt < 4; nt++)
#pragma unroll
            for (int q = 0; q < 4; q++) Sa[nt][q] = 0.0f;

#pragma unroll
        for (int ks = 0; ks < 24; ks++) {
            uint32_t A[4];
            uint32_t aaddr = sQ + (uint32_t)((wm * 16 + lrow + ((grp & 1) << 3)) * SQ_STR
                                             + (ks * 16 + ((grp >> 1) << 3)) * 2);
            LDSM_X4(A[0], A[1], A[2], A[3], aaddr);
#pragma unroll
            for (int ntp = 0; ntp < 2; ntp++) {
                uint32_t b0, b1, b2, b3;
                uint32_t baddr = sK + (uint32_t)((wn * 32 + ntp * 16 + lrow + ((grp >> 1) << 3)) * SK_STR
                                                 + (ks * 16 + ((grp & 1) << 3)) * 2);
                LDSM_X4(b0, b1, b2, b3, baddr);
                MMA_BF16(Sa[2 * ntp],     A, b0, b1);
                MMA_BF16(Sa[2 * ntp + 1], A, b2, b3);
            }
        }

        if (kt == qi) {
#pragma unroll
            for (int nt = 0; nt < 4; nt++) {
                int tb = wn * 32 + nt * 8 + 2 * (lane & 3);
                if (tb     > ra)     Sa[nt][0] = -1e30f;
                if (tb + 1 > ra)     Sa[nt][1] = -1e30f;
                if (tb     > ra + 8) Sa[nt][2] = -1e30f;
                if (tb + 1 > ra + 8) Sa[nt][3] = -1e30f;
            }
        }

        float hm0 = -1e30f, hm1 = -1e30f;
#pragma unroll
        for (int nt = 0; nt < 4; nt++) {
            hm0 = fmaxf(hm0, fmaxf(Sa[nt][0], Sa[nt][1]));
            hm1 = fmaxf(hm1, fmaxf(Sa[nt][2], Sa[nt][3]));
        }
        hm0 = fmaxf(hm0, __shfl_xor_sync(0xffffffffu, hm0, 1));
        hm0 = fmaxf(hm0, __shfl_xor_sync(0xffffffffu, hm0, 2));
        hm1 = fmaxf(hm1, __shfl_xor_sync(0xffffffffu, hm1, 1));
        hm1 = fmaxf(hm1, __shfl_xor_sync(0xffffffffu, hm1, 2));

        float mn0 = fmaxf(m0, hm0), mn1 = fmaxf(m1, hm1);
        float al0 = __expf(m0 - mn0), al1 = __expf(m1 - mn1);
        m0 = mn0; m1 = mn1;

        float hs0 = 0.0f, hs1 = 0.0f;
#pragma unroll
        for (int nt = 0; nt < 4; nt++) {
            Sa[nt][0] = __expf(Sa[nt][0] - mn0); hs0 += Sa[nt][0];
            Sa[nt][1] = __expf(Sa[nt][1] - mn0); hs0 += Sa[nt][1];
            Sa[nt][2] = __expf(Sa[nt][2] - mn1); hs1 += Sa[nt][2];
            Sa[nt][3] = __expf(Sa[nt][3] - mn1); hs1 += Sa[nt][3];
        }
        hs0 += __shfl_xor_sync(0xffffffffu, hs0, 1);
        hs0 += __shfl_xor_sync(0xffffffffu, hs0, 2);
        hs1 += __shfl_xor_sync(0xffffffffu, hs1, 1);
        hs1 += __shfl_xor_sync(0xffffffffu, hs1, 2);
        l0 = l0 * al0 + hs0;
        l1 = l1 * al1 + hs1;
#pragma unroll
        for (int j = 0; j < 16; j++) {
            Oc[j][0] *= al0; Oc[j][1] *= al0;
            Oc[j][2] *= al1; Oc[j][3] *= al1;
        }

        __syncwarp();
#pragma unroll
        for (int nt = 0; nt < 4; nt++) {
            int tl0 = wn * 32 + nt * 8 + 2 * (lane & 3);
#pragma unroll
            for (int q = 0; q < 4; q++) {
                int row = ra + ((q >> 1) << 3);
                int t = tl0 + (q & 1);
                float p = Sa[nt][q];
                __nv_bfloat16 hi = __float2bfloat16_rn(p);
                __nv_bfloat16 lo = __float2bfloat16_rn(p - __bfloat162float(hi));
                uint16_t hb = __bfloat16_as_ushort(hi);
                uint16_t lb = __bfloat16_as_ushort(lo);
                uint32_t ad = sP + (uint32_t)(row * SP_STR + t * 6);
                asm volatile("st.shared.u16 [%0], %1;" :: "r"(ad),     "h"(hb));
                asm volatile("st.shared.u16 [%0], %1;" :: "r"(ad + 2), "h"(lb));
                asm volatile("st.shared.u16 [%0], %1;" :: "r"(ad + 4), "h"(hb));
            }
        }
        __syncwarp();

#pragma unroll
        for (int ks2 = 0; ks2 < 6; ks2++) {
            uint32_t A[4];
            uint32_t aaddr = sP + (uint32_t)((wm * 16 + lrow + ((grp & 1) << 3)) * SP_STR
                                             + (wn * 96 + ks2 * 16 + ((grp >> 1) << 3)) * 2);
            LDSM_X4(A[0], A[1], A[2], A[3], aaddr);
#pragma unroll
            for (int ntp = 0; ntp < 8; ntp++) {
                uint32_t b0, b1, b2, b3;
                uint32_t baddr = sV + (uint32_t)((wn * 96 + ks2 * 16 + lrow + ((grp & 1) << 3)) * SV_STR
                                                 + (ntp * 16 + ((grp >> 1) << 3)) * 2);
                LDSM_X4_T(b0, b1, b2, b3, baddr);
                MMA_BF16(Oc[2 * ntp],     A, b0, b1);
                MMA_BF16(Oc[2 * ntp + 1], A, b2, b3);
            }
        }
    }

    __syncthreads();
    if (wn == 1) {
#pragma unroll
        for (int nt = 0; nt < 16; nt++) {
            int col = nt * 8 + 2 * (lane & 3);
            *(float2*)&mergeO[ra * 128 + col]       = make_float2(Oc[nt][0], Oc[nt][1]);
            *(float2*)&mergeO[(ra + 8) * 128 + col] = make_float2(Oc[nt][2], Oc[nt][3]);
        }
        if ((lane & 3) == 0) {
            mergeM[ra] = m0;     mergeM[ra + 8] = m1;
            mergeL[ra] = l0;     mergeL[ra + 8] = l1;
        }
    }
    __syncthreads();
    if (wn == 0) {
        float M1a = mergeM[ra],     L1a = mergeL[ra];
        float M1b = mergeM[ra + 8], L1b = mergeL[ra + 8];
        float Ma = fmaxf(m0, M1a);
        float w0a = __expf(m0 - Ma), w1a = __expf(M1a - Ma);
        float inva = 1.0f / (l0 * w0a + L1a * w1a);
        float Mb = fmaxf(m1, M1b);
        float w0b = __expf(m1 - Mb), w1b = __expf(M1b - Mb);
        float invb = 1.0f / (l1 * w0b + L1b * w1b);

        size_t obase = ((size_t)(b * SEQ + q0)) * DIM + h * HD;
#pragma unroll
        for (int nt = 0; nt < 16; nt++) {
            int col = nt * 8 + 2 * (lane & 3);
            float2 o1a = *(float2*)&mergeO[ra * 128 + col];
            float2 o1b = *(float2*)&mergeO[(ra + 8) * 128 + col];
            float2 oa = make_float2((Oc[nt][0] * w0a + o1a.x * w1a) * inva,
                                    (Oc[nt][1] * w0a + o1a.y * w1a) * inva);
            float2 ob = make_float2((Oc[nt][2] * w0b + o1b.x * w1b) * invb,
                                    (Oc[nt][3] * w0b + o1b.y * w1b) * invb);
            *(float2*)&Oout[obase + (size_t)ra * DIM + col]       = oa;
            *(float2*)&Oout[obase + (size_t)(ra + 8) * DIM + col] = ob;
        }
    }
}

// ---------------------------------------------------------------------------
extern "C" void kernel_launch(void* const* d_in, const int* in_sizes, int n_in,
                              void* d_out, int out_size)
{
    const float* x  = (const float*)d_in[0];
    const float* wq = (const float*)d_in[1];
    const float* wk = (const float*)d_in[2];
    const float* wv = (const float*)d_in[3];
    const float* wo = (const float*)d_in[4];
    const float* fc = (const float*)d_in[5];
    const float* fs = (const float*)d_in[6];
    float* out = (float*)d_out;

    float *qp, *kp, *vp, *ap;
    uint16_t *xs, *as, *wqs, *wks, *wvs, *wos, *qs2, *ks2, *vs2;
    cudaGetSymbolAddress((void**)&qp, g_q);
    cudaGetSymbolAddress((void**)&kp, g_k);
    cudaGetSymbolAddress((void**)&vp, g_v);
    cudaGetSymbolAddress((void**)&ap, g_attn);
    cudaGetSymbolAddress((void**)&xs, g_xs);
    cudaGetSymbolAddress((void**)&as, g_as);
    cudaGetSymbolAddress((void**)&wqs, g_wqs);
    cudaGetSymbolAddress((void**)&wks, g_wks);
    cudaGetSymbolAddress((void**)&wvs, g_wvs);
    cudaGetSymbolAddress((void**)&wos, g_wos);
    cudaGetSymbolAddress((void**)&qs2, g_qs2);
    cudaGetSymbolAddress((void**)&ks2, g_ks2);
    cudaGetSymbolAddress((void**)&vs2, g_vs2);

    cudaFuncSetAttribute(gemm_hmma, cudaFuncAttributeMaxDynamicSharedMemorySize, GSMEM);
    cudaFuncSetAttribute(attn_mma, cudaFuncAttributeMaxDynamicSharedMemorySize, ATT_SMEM);

    // Split inputs for projections
    {
        int t8_big = MROWS * DIM / 8;
        int t8_kv  = KVDIM * DIM / 8;
        split_kernel<1><<<t8_big / 256, 256>>>(x,  xs,  t8_big);
        split_kernel<0><<<t8_big / 256, 256>>>(wq, wqs, t8_big);
        split_kernel<0><<<t8_kv  / 256, 256>>>(wk, wks, t8_kv);
        split_kernel<0><<<t8_kv  / 256, 256>>>(wv, wvs, t8_kv);
        split_kernel<0><<<t8_big / 256, 256>>>(wo, wos, t8_big);
    }

    // QKV projections (HMMA, 256x128 tiles)
    gemm_hmma<<<dim3(DIM   / 128, MROWS / 256), 256, GSMEM>>>(xs, wqs, qp, MROWS, DIM);
    gemm_hmma<<<dim3(KVDIM / 128, MROWS / 256), 256, GSMEM>>>(xs, wks, kp, MROWS, KVDIM);
    gemm_hmma<<<dim3(KVDIM / 128, MROWS / 256), 256, GSMEM>>>(xs, wvs, vp, MROWS, KVDIM);

    // RoPE + split for attention operands
    rope_split<1><<<(BATCH * NH  * SEQ * 16) / 256, 256>>>(qp, qs2, fc, fs);
    rope_split<0><<<(BATCH * NKV * SEQ * 16) / 256, 256>>>(kp, ks2, fc, fs);
    split_v_kernel<<<(BATCH * NKV * SEQ * 16) / 256, 256>>>(vp, vs2);

    // HMMA flash attention
    attn_mma<<<dim3(SEQ / 64, BATCH * NH), 256, ATT_SMEM>>>(qs2, ks2, vs2, ap);

    // Output projection
    split_kernel<1><<<(MROWS * DIM / 8) / 256, 256>>>(ap, as, MROWS * DIM / 8);
    gemm_hmma<<<dim3(DIM / 128, MROWS / 256), 256, GSMEM>>>(as, wos, out, MROWS, DIM);
}

// round 7
// speedup vs baseline: 1.1013x; 1.1013x over previous
#include <cuda_runtime.h>
#include <cuda_bf16.h>
#include <math.h>
#include <stdint.h>

#define BATCH 2
#define SEQ   2048
#define DIM   4096
#define NH    32
#define NKV   8
#define HD    128
#define MROWS 4096   // BATCH*SEQ
#define KVDIM 1024   // NKV*HD
#define K3    (3 * DIM)   // 12288: split-interleaved K

// ---------------- scratch (zero-init .bss, no runtime allocation) ----------
__device__ uint16_t g_xs [(size_t)MROWS * K3];   // x split (A-side)
__device__ uint16_t g_as [(size_t)MROWS * K3];   // attn-out split (A-side)
__device__ uint16_t g_wqs[(size_t)DIM   * K3];   // weight splits (B-side)
__device__ uint16_t g_wks[(size_t)KVDIM * K3];
__device__ uint16_t g_wvs[(size_t)KVDIM * K3];
__device__ uint16_t g_wos[(size_t)DIM   * K3];

// attention split operands (written directly by QKV gemm epilogues)
__device__ uint16_t g_qs2[(size_t)BATCH * NH  * SEQ * 384];
__device__ uint16_t g_ks2[(size_t)BATCH * NKV * SEQ * 384];
__device__ uint16_t g_vs2[(size_t)BATCH * NKV * (3*SEQ) * HD];

// ---------------- helpers ---------------------------------------------------
__device__ __forceinline__ uint32_t smem_u32(const void* p) {
    return (uint32_t)__cvta_generic_to_shared(p);
}
__device__ __forceinline__ void cp_async16(uint32_t dst, const void* src) {
    asm volatile("cp.async.cg.shared.global [%0], [%1], 16;" :: "r"(dst), "l"(src) : "memory");
}
__device__ __forceinline__ void cp_commit() {
    asm volatile("cp.async.commit_group;" ::: "memory");
}

#define LDSM_X4(r0, r1, r2, r3, addr) \
    asm volatile("ldmatrix.sync.aligned.m8n8.x4.shared.b16 {%0,%1,%2,%3}, [%4];" \
                 : "=r"(r0), "=r"(r1), "=r"(r2), "=r"(r3) : "r"(addr))

#define LDSM_X4_T(r0, r1, r2, r3, addr) \
    asm volatile("ldmatrix.sync.aligned.m8n8.x4.trans.shared.b16 {%0,%1,%2,%3}, [%4];" \
                 : "=r"(r0), "=r"(r1), "=r"(r2), "=r"(r3) : "r"(addr))

#define MMA_BF16(d, a, b0v, b1v) \
    asm volatile("mma.sync.aligned.m16n8k16.row.col.f32.bf16.bf16.f32 " \
                 "{%0,%1,%2,%3}, {%4,%5,%6,%7}, {%8,%9}, {%0,%1,%2,%3};" \
                 : "+f"((d)[0]), "+f"((d)[1]), "+f"((d)[2]), "+f"((d)[3]) \
                 : "r"((a)[0]), "r"((a)[1]), "r"((a)[2]), "r"((a)[3]), \
                   "r"(b0v), "r"(b1v))

__device__ __forceinline__ void split2(float f, uint16_t& hb, uint16_t& lb) {
    __nv_bfloat16 hi = __float2bfloat16_rn(f);
    __nv_bfloat16 lo = __float2bfloat16_rn(f - __bfloat162float(hi));
    hb = __bfloat16_as_ushort(hi);
    lb = __bfloat16_as_ushort(lo);
}

// ---------------------------------------------------------------------------
// Split fp32 -> bf16 triplets. AMODE=1: (hi,lo,hi); AMODE=0: (hi,hi,lo).
// ---------------------------------------------------------------------------
template <int AMODE>
__global__ void split_kernel(const float* __restrict__ src, uint16_t* __restrict__ dst,
                             int total8)
{
    int t = blockIdx.x * blockDim.x + threadIdx.x;
    if (t >= total8) return;
    float4 v0 = *(const float4*)&src[(size_t)t * 8];
    float4 v1 = *(const float4*)&src[(size_t)t * 8 + 4];
    float f[8] = {v0.x, v0.y, v0.z, v0.w, v1.x, v1.y, v1.z, v1.w};
    __align__(16) uint16_t o[24];
#pragma unroll
    for (int j = 0; j < 8; j++) {
        uint16_t hb, lb;
        split2(f[j], hb, lb);
        if (AMODE) { o[3*j] = hb; o[3*j+1] = lb; o[3*j+2] = hb; }
        else       { o[3*j] = hb; o[3*j+1] = hb; o[3*j+2] = lb; }
    }
    uint4* dp = (uint4*)&dst[(size_t)t * 24];
    dp[0] = *(uint4*)&o[0];
    dp[1] = *(uint4*)&o[8];
    dp[2] = *(uint4*)&o[16];
}

// ---------------------------------------------------------------------------
// HMMA bf16 GEMM (R5 config: 128x128 CTA, warp 32x64, 4-stage, 2 CTAs/SM)
// EPI: 0 = plain fp32 C store; 1 = Q rope+scale+split -> g_qs2;
//      2 = K rope+split -> g_ks2; 3 = V split -> g_vs2
// ---------------------------------------------------------------------------
#define BKC         32
#define ROW_BYTES   80
#define STAGE_BYTES (256 * ROW_BYTES)
#define NSTAGE      4
#define GSMEM       (NSTAGE * STAGE_BYTES)   // 81920 -> 2 CTAs/SM
#define NITER       (K3 / BKC)               // 384

template <int EPI>
__global__ void __launch_bounds__(256) gemm_hmma(
    const uint16_t* __restrict__ A, const uint16_t* __restrict__ Bm,
    float* __restrict__ C, uint16_t* __restrict__ D16,
    const float* __restrict__ fc, const float* __restrict__ fs, int N)
{
    extern __shared__ __align__(1024) char smem[];
    const uint32_t sbase = smem_u32(smem);

    const int bm = blockIdx.y * 128;
    const int bn = blockIdx.x * 128;
    const int tid = threadIdx.x;
    const int wid = tid >> 5;
    const int lane = tid & 31;
    const int wm = wid & 3;
    const int wn = wid >> 2;

    const uint16_t* ga0 = A  + (size_t)bm * K3;
    const uint16_t* gb0 = Bm + (size_t)bn * K3;

    const int lc = tid & 3;
    const int lr = tid >> 2;

    auto load_stage = [&](int s, int chunk) {
        const uint32_t sa = sbase + (uint32_t)s * STAGE_BYTES;
        const size_t koff = (size_t)chunk * BKC + lc * 8;
#pragma unroll
        for (int j = 0; j < 4; j++) {
            int r = lr + j * 64;
            const uint16_t* src = (r < 128)
                ? ga0 + (size_t)r * K3 + koff
                : gb0 + (size_t)(r - 128) * K3 + koff;
            cp_async16(sa + (uint32_t)(r * ROW_BYTES + lc * 16), src);
        }
        cp_commit();
    };

    float d[2][8][4];
#pragma unroll
    for (int mi = 0; mi < 2; mi++)
#pragma unroll
        for (int nj = 0; nj < 8; nj++)
#pragma unroll
            for (int q = 0; q < 4; q++) d[mi][nj][q] = 0.0f;

    const int grp  = lane >> 3;
    const int lrow = lane & 7;
    const int a_r = lrow + ((grp & 1) << 3);
    const int a_c = (grp >> 1) << 3;
    const int b_r = lrow + ((grp >> 1) << 3);
    const int b_c = (grp & 1) << 3;

    load_stage(0, 0);
    load_stage(1, 1);
    load_stage(2, 2);

    for (int i = 0; i < NITER; i++) {
        const int s = i & (NSTAGE - 1);
        asm volatile("cp.async.wait_group %0;" :: "n"(NSTAGE - 2) : "memory");
        __syncthreads();
        if (i + 3 < NITER) load_stage((i + 3) & (NSTAGE - 1), i + 3);
        else cp_commit();

        const uint32_t aB = sbase + (uint32_t)s * STAGE_BYTES;
        const uint32_t bB = aB + 128 * ROW_BYTES;
#pragma unroll
        for (int step = 0; step < 2; step++) {
            uint32_t af[2][4];
#pragma unroll
            for (int mi = 0; mi < 2; mi++) {
                uint32_t addr = aB + (uint32_t)((wm * 32 + mi * 16 + a_r) * ROW_BYTES
                                                + (step * 16 + a_c) * 2);
                LDSM_X4(af[mi][0], af[mi][1], af[mi][2], af[mi][3], addr);
            }
#pragma unroll
            for (int njp = 0; njp < 4; njp++) {
                uint32_t b0, b1, b2, b3;
                uint32_t addr = bB + (uint32_t)((wn * 64 + njp * 16 + b_r) * ROW_BYTES
                                                + (step * 16 + b_c) * 2);
                LDSM_X4(b0, b1, b2, b3, addr);
#pragma unroll
                for (int mi = 0; mi < 2; mi++) {
                    MMA_BF16(d[mi][2 * njp],     af[mi], b0, b1);
                    MMA_BF16(d[mi][2 * njp + 1], af[mi], b2, b3);
                }
            }
        }
    }

    // ------------------- epilogue -------------------
    const int er = lane >> 2;
    const int ec = (lane & 3) * 2;

#pragma unroll
    for (int mi = 0; mi < 2; mi++) {
#pragma unroll
        for (int nj = 0; nj < 8; nj++) {
            const int r0 = bm + wm * 32 + mi * 16 + er;   // global row (m)
            const int c0 = bn + wn * 64 + nj * 8 + ec;    // global col (even)

            if (EPI == 0) {
                *(float2*)&C[(size_t)r0 * N + c0]       = make_float2(d[mi][nj][0], d[mi][nj][1]);
                *(float2*)&C[(size_t)(r0 + 8) * N + c0] = make_float2(d[mi][nj][2], d[mi][nj][3]);
            } else if (EPI == 3) {
                // V split: rows 3t, 3t+1 = hi pair; 3t+2 = lo pair
                const int kv = c0 >> 7, dl = c0 & 127;
#pragma unroll
                for (int half = 0; half < 2; half++) {
                    int m = r0 + half * 8;
                    int b = m >> 11, t = m & (SEQ - 1);
                    float v0 = d[mi][nj][2 * half], v1 = d[mi][nj][2 * half + 1];
                    uint16_t h0, l0, h1, l1;
                    split2(v0, h0, l0);
                    split2(v1, h1, l1);
                    uint32_t hp = (uint32_t)h0 | ((uint32_t)h1 << 16);
                    uint32_t lp = (uint32_t)l0 | ((uint32_t)l1 << 16);
                    uint16_t* base = g_vs2 + ((size_t)(b * NKV + kv) * (3 * SEQ) + 3 * t) * HD + dl;
                    *(uint32_t*)&base[0]      = hp;
                    *(uint32_t*)&base[HD]     = hp;
                    *(uint32_t*)&base[2 * HD] = lp;
                }
            } else {
                // Q (EPI==1) / K (EPI==2): rope + split
                const int h = c0 >> 7, dl = c0 & 127;
                const int ip = dl >> 1;                   // rope pair index
#pragma unroll
                for (int half = 0; half < 2; half++) {
                    int m = r0 + half * 8;
                    int b = m >> 11, s = m & (SEQ - 1);
                    float cv = fc[s * 64 + ip];
                    float sv = fs[s * 64 + ip];
                    float xr = d[mi][nj][2 * half], xi = d[mi][nj][2 * half + 1];
                    float rr = xr * cv - xi * sv;
                    float ri = xr * sv + xi * cv;
                    if (EPI == 1) { rr *= 0.08838834764831845f; ri *= 0.08838834764831845f; }
                    uint16_t hr, lr2, hi2, li;
                    split2(rr, hr, lr2);
                    split2(ri, hi2, li);
                    uint16_t o[6];
                    if (EPI == 1) { o[0]=hr; o[1]=lr2; o[2]=hr; o[3]=hi2; o[4]=li; o[5]=hi2; }
                    else          { o[0]=hr; o[1]=hr; o[2]=lr2; o[3]=hi2; o[4]=hi2; o[5]=li; }
                    size_t rowo = (EPI == 1)
                        ? ((size_t)(b * NH  + h) * SEQ + s)
                        : ((size_t)(b * NKV + h) * SEQ + s);
                    uint16_t* dp = (EPI == 1 ? g_qs2 : g_ks2) + rowo * 384 + dl * 3;
                    *(uint32_t*)&dp[0] = (uint32_t)o[0] | ((uint32_t)o[1] << 16);
                    *(uint32_t*)&dp[2] = (uint32_t)o[2] | ((uint32_t)o[3] << 16);
                    *(uint32_t*)&dp[4] = (uint32_t)o[4] | ((uint32_t)o[5] << 16);
                }
            }
        }
    }
}

// ---------------------------------------------------------------------------
// HMMA causal flash attention (R5 core; epilogue now writes split triplets
// directly to g_as in A-side (hi,lo,hi) interleaved format)
// ---------------------------------------------------------------------------
#define SQ_STR   784
#define SK_STR   784
#define SV_STR   272
#define SP_STR   400
#define SQ_OFF   0
#define SK_OFF   50176
#define SV_OFF   100352
#define SP_OFF   152576
#define ATT_SMEM 178176

__global__ void __launch_bounds__(256) attn_mma(
    const uint16_t* __restrict__ Qs, const uint16_t* __restrict__ Ks,
    const uint16_t* __restrict__ Vs, uint16_t* __restrict__ Oas)
{
    extern __shared__ __align__(1024) char smem[];
    const uint32_t sQ = smem_u32(smem) + SQ_OFF;
    const uint32_t sK = smem_u32(smem) + SK_OFF;
    const uint32_t sV = smem_u32(smem) + SV_OFF;
    const uint32_t sP = smem_u32(smem) + SP_OFF;
    float* mergeO = (float*)smem;
    float* mergeM = (float*)(smem + 32768);
    float* mergeL = (float*)(smem + 32768 + 256);

    const int qi = (SEQ / 64 - 1) - blockIdx.x;
    const int bh = blockIdx.y;
    const int b = bh >> 5, h = bh & 31, kvh = h >> 2;
    const int q0 = qi * 64;
    const int tid = threadIdx.x;
    const int wid = tid >> 5, lane = tid & 31;
    const int wm = wid & 3, wn = wid >> 2;
    const int grp = lane >> 3, lrow = lane & 7;

    const uint16_t* gq = Qs + ((size_t)(b * NH + h) * SEQ + q0) * 384;
#pragma unroll
    for (int j = 0; j < 12; j++) {
        int id = tid + j * 256;
        int r = id / 48, c = id % 48;
        cp_async16(sQ + (uint32_t)(r * SQ_STR + c * 16), gq + (size_t)r * 384 + c * 8);
    }
    cp_commit();

    float m0 = -1e30f, m1 = -1e30f, l0 = 0.0f, l1 = 0.0f;
    float Oc[16][4];
#pragma unroll
    for (int j = 0; j < 16; j++)
#pragma unroll
        for (int q = 0; q < 4; q++) Oc[j][q] = 0.0f;

    const uint16_t* gk = Ks + ((size_t)(b * NKV + kvh) * SEQ) * 384;
    const uint16_t* gv = Vs + ((size_t)(b * NKV + kvh) * (3 * SEQ)) * HD;

    const int ra = wm * 16 + (lane >> 2);

    for (int kt = 0; kt <= qi; kt++) {
        const int t0 = kt * 64;
        __syncthreads();
#pragma unroll
        for (int j = 0; j < 12; j++) {
            int id = tid + j * 256;
            int r = id / 48, c = id % 48;
            cp_async16(sK + (uint32_t)(r * SK_STR + c * 16),
                       gk + ((size_t)(t0 + r)) * 384 + c * 8);
        }
#pragma unroll
        for (int j = 0; j < 12; j++) {
            int id = tid + j * 256;
            int r = id / 16, c = id % 16;
            cp_async16(sV + (uint32_t)(r * SV_STR + c * 16),
                       gv + ((size_t)(t0 * 3 + r)) * HD + c * 8);
        }
        cp_commit();
        asm volatile("cp.async.wait_group 0;" ::: "memory");
        __syncthreads();

        float Sa[4][4];
#pragma unroll
        for (int nt = 0; nt < 4; nt++)
#pragma unroll
            for (int q = 0; q < 4; q++) Sa[nt][q] = 0.0f;

#pragma unroll
        for (int ks = 0; ks < 24; ks++) {
            uint32_t A[4];
            uint32_t aaddr = sQ + (uint32_t)((wm * 16 + lrow + ((grp & 1) << 3)) * SQ_STR
                                             + (ks * 16 + ((grp >> 1) << 3)) * 2);
            LDSM_X4(A[0], A[1], A[2], A[3], aaddr);
#pragma unroll
            for (int ntp = 0; ntp < 2; ntp++) {
                uint32_t b0, b1, b2, b3;
                uint32_t baddr = sK + (uint32_t)((wn * 32 + ntp * 16 + lrow + ((grp >> 1) << 3)) * SK_STR
                                                 + (ks * 16 + ((grp & 1) << 3)) * 2);
                LDSM_X4(b0, b1, b2, b3, baddr);
                MMA_BF16(Sa[2 * ntp],     A, b0, b1);
                MMA_BF16(Sa[2 * ntp + 1], A, b2, b3);
            }
        }

        if (kt == qi) {
#pragma unroll
            for (int nt = 0; nt < 4; nt++) {
                int tb = wn * 32 + nt * 8 + 2 * (lane & 3);
                if (tb     > ra)     Sa[nt][0] = -1e30f;
                if (tb + 1 > ra)     Sa[nt][1] = -1e30f;
                if (tb     > ra + 8) Sa[nt][2] = -1e30f;
                if (tb + 1 > ra + 8) Sa[nt][3] = -1e30f;
            }
        }

        float hm0 = -1e30f, hm1 = -1e30f;
#pragma unroll
        for (int nt = 0; nt < 4; nt++) {
            hm0 = fmaxf(hm0, fmaxf(Sa[nt][0], Sa[nt][1]));
            hm1 = fmaxf(hm1, fmaxf(Sa[nt][2], Sa[nt][3]));
        }
        hm0 = fmaxf(hm0, __shfl_xor_sync(0xffffffffu, hm0, 1));
        hm0 = fmaxf(hm0, __shfl_xor_sync(0xffffffffu, hm0, 2));
        hm1 = fmaxf(hm1, __shfl_xor_sync(0xffffffffu, hm1, 1));
        hm1 = fmaxf(hm1, __shfl_xor_sync(0xffffffffu, hm1, 2));

        float mn0 = fmaxf(m0, hm0), mn1 = fmaxf(m1, hm1);
        float al0 = __expf(m0 - mn0), al1 = __expf(m1 - mn1);
        m0 = mn0; m1 = mn1;

        float hs0 = 0.0f, hs1 = 0.0f;
#pragma unroll
        for (int nt = 0; nt < 4; nt++) {
            Sa[nt][0] = __expf(Sa[nt][0] - mn0); hs0 += Sa[nt][0];
            Sa[nt][1] = __expf(Sa[nt][1] - mn0); hs0 += Sa[nt][1];
            Sa[nt][2] = __expf(Sa[nt][2] - mn1); hs1 += Sa[nt][2];
            Sa[nt][3] = __expf(Sa[nt][3] - mn1); hs1 += Sa[nt][3];
        }
        hs0 += __shfl_xor_sync(0xffffffffu, hs0, 1);
        hs0 += __shfl_xor_sync(0xffffffffu, hs0, 2);
        hs1 += __shfl_xor_sync(0xffffffffu, hs1, 1);
        hs1 += __shfl_xor_sync(0xffffffffu, hs1, 2);
        l0 = l0 * al0 + hs0;
        l1 = l1 * al1 + hs1;
#pragma unroll
        for (int j = 0; j < 16; j++) {
            Oc[j][0] *= al0; Oc[j][1] *= al0;
            Oc[j][2] *= al1; Oc[j][3] *= al1;
        }

        __syncwarp();
#pragma unroll
        for (int nt = 0; nt < 4; nt++) {
            int tl0 = wn * 32 + nt * 8 + 2 * (lane & 3);
#pragma unroll
            for (int q = 0; q < 4; q++) {
                int row = ra + ((q >> 1) << 3);
                int t = tl0 + (q & 1);
                float p = Sa[nt][q];
                uint16_t hb, lb;
                split2(p, hb, lb);
                uint32_t ad = sP + (uint32_t)(row * SP_STR + t * 6);
                asm volatile("st.shared.u16 [%0], %1;" :: "r"(ad),     "h"(hb));
                asm volatile("st.shared.u16 [%0], %1;" :: "r"(ad + 2), "h"(lb));
                asm volatile("st.shared.u16 [%0], %1;" :: "r"(ad + 4), "h"(hb));
            }
        }
        __syncwarp();

#pragma unroll
        for (int ks2 = 0; ks2 < 6; ks2++) {
            uint32_t A[4];
            uint32_t aaddr = sP + (uint32_t)((wm * 16 + lrow + ((grp & 1) << 3)) * SP_STR
                                             + (wn * 96 + ks2 * 16 + ((grp >> 1) << 3)) * 2);
            LDSM_X4(A[0], A[1], A[2], A[3], aaddr);
#pragma unroll
            for (int ntp = 0; ntp < 8; ntp++) {
                uint32_t b0, b1, b2, b3;
                uint32_t baddr = sV + (uint32_t)((wn * 96 + ks2 * 16 + lrow + ((grp & 1) << 3)) * SV_STR
                                                 + (ntp * 16 + ((grp >> 1) << 3)) * 2);
                LDSM_X4_T(b0, b1, b2, b3, baddr);
                MMA_BF16(Oc[2 * ntp],     A, b0, b1);
                MMA_BF16(Oc[2 * ntp + 1], A, b2, b3);
            }
        }
    }

    // ---- merge halves + write A-side split triplets to g_as ----
    __syncthreads();
    if (wn == 1) {
#pragma unroll
        for (int nt = 0; nt < 16; nt++) {
            int col = nt * 8 + 2 * (lane & 3);
            *(float2*)&mergeO[ra * 128 + col]       = make_float2(Oc[nt][0], Oc[nt][1]);
            *(float2*)&mergeO[(ra + 8) * 128 + col] = make_float2(Oc[nt][2], Oc[nt][3]);
        }
        if ((lane & 3) == 0) {
            mergeM[ra] = m0;     mergeM[ra + 8] = m1;
            mergeL[ra] = l0;     mergeL[ra + 8] = l1;
        }
    }
    __syncthreads();
    if (wn == 0) {
        float M1a = mergeM[ra],     L1a = mergeL[ra];
        float M1b = mergeM[ra + 8], L1b = mergeL[ra + 8];
        float Ma = fmaxf(m0, M1a);
        float w0a = __expf(m0 - Ma), w1a = __expf(M1a - Ma);
        float inva = 1.0f / (l0 * w0a + L1a * w1a);
        float Mb = fmaxf(m1, M1b);
        float w0b = __expf(m1 - Mb), w1b = __expf(M1b - Mb);
        float invb = 1.0f / (l1 * w0b + L1b * w1b);

        const int m0g = b * SEQ + q0 + ra;        // global row for half a
        const int m1g = m0g + 8;                  // half b
#pragma unroll
        for (int nt = 0; nt < 16; nt++) {
            int col = nt * 8 + 2 * (lane & 3);
            float2 o1a = *(float2*)&mergeO[ra * 128 + col];
            float2 o1b = *(float2*)&mergeO[(ra + 8) * 128 + col];
            float oa0 = (Oc[nt][0] * w0a + o1a.x * w1a) * inva;
            float oa1 = (Oc[nt][1] * w0a + o1a.y * w1a) * inva;
            float ob0 = (Oc[nt][2] * w0b + o1b.x * w1b) * invb;
            float ob1 = (Oc[nt][3] * w0b + o1b.y * w1b) * invb;

            int cg = h * HD + col;                // global feature col (even)
            uint16_t h0, l0v, h1, l1v;
            // half a
            split2(oa0, h0, l0v);
            split2(oa1, h1, l1v);
            uint16_t* dp = Oas + (size_t)m0g * K3 + (size_t)cg * 3;
            *(uint32_t*)&dp[0] = (uint32_t)h0 | ((uint32_t)l0v << 16);
            *(uint32_t*)&dp[2] = (uint32_t)h0 | ((uint32_t)h1 << 16);
            *(uint32_t*)&dp[4] = (uint32_t)l1v | ((uint32_t)h1 << 16);
            // half b
            split2(ob0, h0, l0v);
            split2(ob1, h1, l1v);
            dp = Oas + (size_t)m1g * K3 + (size_t)cg * 3;
            *(uint32_t*)&dp[0] = (uint32_t)h0 | ((uint32_t)l0v << 16);
            *(uint32_t*)&dp[2] = (uint32_t)h0 | ((uint32_t)h1 << 16);
            *(uint32_t*)&dp[4] = (uint32_t)l1v | ((uint32_t)h1 << 16);
        }
    }
}

// ---------------------------------------------------------------------------
extern "C" void kernel_launch(void* const* d_in, const int* in_sizes, int n_in,
                              void* d_out, int out_size)
{
    const float* x  = (const float*)d_in[0];
    const float* wq = (const float*)d_in[1];
    const float* wk = (const float*)d_in[2];
    const float* wv = (const float*)d_in[3];
    const float* wo = (const float*)d_in[4];
    const float* fc = (const float*)d_in[5];
    const float* fs = (const float*)d_in[6];
    float* out = (float*)d_out;

    uint16_t *xs, *as, *wqs, *wks, *wvs, *wos, *qs2, *ks2, *vs2;
    cudaGetSymbolAddress((void**)&xs, g_xs);
    cudaGetSymbolAddress((void**)&as, g_as);
    cudaGetSymbolAddress((void**)&wqs, g_wqs);
    cudaGetSymbolAddress((void**)&wks, g_wks);
    cudaGetSymbolAddress((void**)&wvs, g_wvs);
    cudaGetSymbolAddress((void**)&wos, g_wos);
    cudaGetSymbolAddress((void**)&qs2, g_qs2);
    cudaGetSymbolAddress((void**)&ks2, g_ks2);
    cudaGetSymbolAddress((void**)&vs2, g_vs2);

    cudaFuncSetAttribute(gemm_hmma<0>, cudaFuncAttributeMaxDynamicSharedMemorySize, GSMEM);
    cudaFuncSetAttribute(gemm_hmma<1>, cudaFuncAttributeMaxDynamicSharedMemorySize, GSMEM);
    cudaFuncSetAttribute(gemm_hmma<2>, cudaFuncAttributeMaxDynamicSharedMemorySize, GSMEM);
    cudaFuncSetAttribute(gemm_hmma<3>, cudaFuncAttributeMaxDynamicSharedMemorySize, GSMEM);
    cudaFuncSetAttribute(attn_mma, cudaFuncAttributeMaxDynamicSharedMemorySize, ATT_SMEM);

    // Split inputs for projections
    {
        int t8_big = MROWS * DIM / 8;
        int t8_kv  = KVDIM * DIM / 8;
        split_kernel<1><<<t8_big / 256, 256>>>(x,  xs,  t8_big);
        split_kernel<0><<<t8_big / 256, 256>>>(wq, wqs, t8_big);
        split_kernel<0><<<t8_kv  / 256, 256>>>(wk, wks, t8_kv);
        split_kernel<0><<<t8_kv  / 256, 256>>>(wv, wvs, t8_kv);
        split_kernel<0><<<t8_big / 256, 256>>>(wo, wos, t8_big);
    }

    // QKV projections with fused rope/split epilogues
    gemm_hmma<1><<<dim3(DIM   / 128, MROWS / 128), 256, GSMEM>>>(xs, wqs, nullptr, qs2, fc, fs, DIM);
    gemm_hmma<2><<<dim3(KVDIM / 128, MROWS / 128), 256, GSMEM>>>(xs, wks, nullptr, ks2, fc, fs, KVDIM);
    gemm_hmma<3><<<dim3(KVDIM / 128, MROWS / 128), 256, GSMEM>>>(xs, wvs, nullptr, vs2, fc, fs, KVDIM);

    // HMMA flash attention (writes split triplets to g_as)
    attn_mma<<<dim3(SEQ / 64, BATCH * NH), 256, ATT_SMEM>>>(qs2, ks2, vs2, as);

    // Output projection (plain fp32 epilogue)
    gemm_hmma<0><<<dim3(DIM / 128, MROWS / 128), 256, GSMEM>>>(as, wos, out, nullptr, fc, fs, DIM);
}